// round 15
// baseline (speedup 1.0000x reference)
#include <cuda_runtime.h>
#include <cuda_fp16.h>
#include <math.h>
#include <stdint.h>

// ---------------------------------------------------------------------------
// VAE forward. Round 15: R11 structure (3-stage cp.async, 64x64 warp tiles),
// with enc1/dec3 widened to 128x256 CTA tiles (WN=4, 256 thr, 1 CTA/SM,
// 8 warps/SM) to cut L2->SMEM fill bytes 33%. enc2/dec2 keep WN=2 (2 CTA/SM).
// Numerics identical to R8/R11 (rel_err 6.3148e-4).
// ---------------------------------------------------------------------------

#define BATCH 1024
#define IMG   27648
#define H1    900
#define H2    300
#define D     16

#define W1N 1024
#define H1K 960
#define H2N 384
#define H2K 320

enum { ACT_TANH = 2, ACT_RAW = 3 };

// ---------------- scratch ----------------------------------------------------
__device__ float g_ws[4 * BATCH * W1N];

__device__ __align__(16) __half g_xh[(size_t)BATCH * IMG];
__device__ __align__(16) __half g_xl[(size_t)BATCH * IMG];
__device__ __align__(16) __half g_w1h[(size_t)IMG * W1N];
__device__ __align__(16) __half g_h1h[(size_t)BATCH * H1K];
__device__ __align__(16) __half g_h1l[(size_t)BATCH * H1K];
__device__ __align__(16) __half g_w2h[(size_t)H1K * H2N];
__device__ __align__(16) __half g_w2l[(size_t)H1K * H2N];
__device__ __align__(16) __half g_g1h[(size_t)BATCH * H2K];
__device__ __align__(16) __half g_g1l[(size_t)BATCH * H2K];
__device__ __align__(16) __half g_dw2h[(size_t)H2K * H2N];
__device__ __align__(16) __half g_dw2l[(size_t)H2K * H2N];
__device__ __align__(16) __half g_g2h[(size_t)BATCH * H2K];
__device__ __align__(16) __half g_g2l[(size_t)BATCH * H2K];
__device__ __align__(16) __half g_w3h[(size_t)H2K * IMG];
__device__ __align__(16) __half g_w3l[(size_t)H2K * IMG];

// ---------------- element helpers -------------------------------------------
__device__ __forceinline__ void load4(const float* __restrict__ src,
                                      int r, int c, int src_rows, int src_cols,
                                      float v[4])
{
    if (r < src_rows && c + 3 < src_cols) {
        float4 f = *(const float4*)&src[(size_t)r * src_cols + c];
        v[0] = f.x; v[1] = f.y; v[2] = f.z; v[3] = f.w;
    } else {
#pragma unroll
        for (int i = 0; i < 4; i++)
            v[i] = (r < src_rows && c + i < src_cols)
                 ? src[(size_t)r * src_cols + c + i] : 0.f;
    }
}

__device__ __forceinline__ void store_split4(__half* __restrict__ hi,
                                             __half* __restrict__ lo,
                                             size_t o, const float v[4])
{
    __half h4[4], l4[4];
#pragma unroll
    for (int i = 0; i < 4; i++) {
        h4[i] = __float2half_rn(v[i]);
        l4[i] = __float2half_rn(v[i] - __half2float(h4[i]));
    }
    *(uint64_t*)&hi[o] = *(uint64_t*)h4;
    *(uint64_t*)&lo[o] = *(uint64_t*)l4;
}

// ---------------- prep_main: x split (hi/lo) + w1 fp16 conv ----------------
#define PM_X  (27 * BATCH)
#define PM_W1 (PM_X + IMG)

__global__ void prep_main(const float* __restrict__ x,
                          __half* __restrict__ xh, __half* __restrict__ xl,
                          const float* __restrict__ w1, __half* __restrict__ w1h)
{
    int b = blockIdx.x;
    int t = threadIdx.x;
    if (b < PM_X) {
        int r  = b / 27;
        int xb = b - r * 27;
        int c  = (xb * 256 + t) * 4;
        float v[4];
        load4(x, r, c, BATCH, IMG, v);
        store_split4(xh, xl, (size_t)r * IMG + c, v);
    } else {
        int r = b - PM_X;
        int c = t * 4;
        float v[4];
        load4(w1, r, c, IMG, H1, v);
        __half h4[4];
#pragma unroll
        for (int i = 0; i < 4; i++) h4[i] = __float2half_rn(v[i]);
        *(uint64_t*)&w1h[(size_t)r * W1N + c] = *(uint64_t*)h4;
    }
}

// ---------------- prep_rest: w2 / dw2 / w3 splits (forked stream) ----------
#define PR_W2  H1K
#define PR_DW2 (PR_W2 + H2K)
#define PR_W3  (PR_DW2 + 27 * H2K)

__global__ void prep_rest(const float* __restrict__ w2, __half* __restrict__ w2h,
                          __half* __restrict__ w2l,
                          const float* __restrict__ dw2, __half* __restrict__ dw2h,
                          __half* __restrict__ dw2l,
                          const float* __restrict__ w3, __half* __restrict__ w3h,
                          __half* __restrict__ w3l)
{
    int b = blockIdx.x;
    int t = threadIdx.x;
    if (b < PR_W2) {
        int c = t * 4;
        if (c >= H2N) return;
        float v[4];
        load4(w2, b, c, H1, H2, v);
        store_split4(w2h, w2l, (size_t)b * H2N + c, v);
    } else if (b < PR_DW2) {
        int r = b - PR_W2;
        int c = t * 4;
        if (c >= H2N) return;
        float v[4];
        load4(dw2, r, c, H2, H2, v);
        store_split4(dw2h, dw2l, (size_t)r * H2N + c, v);
    } else {
        int bb = b - PR_DW2;
        int xb = bb % 27;
        int r  = bb / 27;
        int c  = (xb * 256 + t) * 4;
        float v[4];
        load4(w3, r, c, H2, IMG, v);
        store_split4(w3h, w3l, (size_t)r * IMG + c, v);
    }
}

// ---------------- tensor-core GEMM (fp16, 64x64 warp tiles) ----------------
// WN = warps along N (2 -> CTA 128x128, 128 thr, 2 CTA/SM;
//                     4 -> CTA 128x256, 256 thr, 1 CTA/SM). 3-stage pipeline.
#define TBM 128
#define TBK 32
#define ASTR 40
#define NSTG 3

#define A_BYTES (TBM * ASTR * 2)                        // 10240
#define BSTR_OF(WN) ((WN) * 64 + 8)
#define B_BYTES_OF(WN) (TBK * BSTR_OF(WN) * 2)
#define STAGE_OF(WN) (2 * A_BYTES + 2 * B_BYTES_OF(WN))
#define SMEM_OF(WN) (NSTG * STAGE_OF(WN))               // WN=2:113664 WN=4:162816

__device__ __forceinline__ void cp16(void* s, const void* g)
{
    uint32_t sa = (uint32_t)__cvta_generic_to_shared(s);
    asm volatile("cp.async.cg.shared.global [%0], [%1], 16;\n" :: "r"(sa), "l"(g));
}

__device__ __forceinline__ void ldsm_x4(uint32_t* r, const void* p)
{
    uint32_t a = (uint32_t)__cvta_generic_to_shared(p);
    asm volatile("ldmatrix.sync.aligned.m8n8.x4.shared.b16 {%0,%1,%2,%3}, [%4];\n"
                 : "=r"(r[0]), "=r"(r[1]), "=r"(r[2]), "=r"(r[3]) : "r"(a));
}

__device__ __forceinline__ void ldsm_x4_t(uint32_t* r, const void* p)
{
    uint32_t a = (uint32_t)__cvta_generic_to_shared(p);
    asm volatile("ldmatrix.sync.aligned.m8n8.x4.trans.shared.b16 {%0,%1,%2,%3}, [%4];\n"
                 : "=r"(r[0]), "=r"(r[1]), "=r"(r[2]), "=r"(r[3]) : "r"(a));
}

__device__ __forceinline__ void mma16816(float* c, const uint32_t* a, const uint32_t* b)
{
    asm volatile(
        "mma.sync.aligned.m16n8k16.row.col.f32.f16.f16.f32 "
        "{%0,%1,%2,%3}, {%4,%5,%6,%7}, {%8,%9}, {%0,%1,%2,%3};\n"
        : "+f"(c[0]), "+f"(c[1]), "+f"(c[2]), "+f"(c[3])
        : "r"(a[0]), "r"(a[1]), "r"(a[2]), "r"(a[3]), "r"(b[0]), "r"(b[1]));
}

// NPROD==2: C = Ah@Bh + Al@Bh ; NPROD==3: + Ah@Bl.
template <int ACT, int NPROD, int WN>
__global__ void __launch_bounds__(WN * 64, 4 / WN)
mma_gemm_big(const __half* __restrict__ Ah, const __half* __restrict__ Al,
             int lda,
             const __half* __restrict__ Bh, const __half* __restrict__ Bl,
             int ldb,
             const float* __restrict__ bias, float* __restrict__ C, int ldc,
             int Nreal, int KT, int kslice_kt)
{
    constexpr int NTHREADS = WN * 64;
    constexpr int BSTR = BSTR_OF(WN);
    constexpr int B_BYTES = B_BYTES_OF(WN);
    constexpr int STAGE_BYTES = STAGE_OF(WN);
    constexpr int TBN = WN * 64;

    extern __shared__ char smem[];
    __half *sAh[NSTG], *sAl[NSTG], *sBh[NSTG], *sBl[NSTG];
#pragma unroll
    for (int s = 0; s < NSTG; s++) {
        char* base = smem + s * STAGE_BYTES;
        sAh[s] = (__half*)(base);
        sAl[s] = (__half*)(base + A_BYTES);
        sBh[s] = (__half*)(base + 2 * A_BYTES);
        sBl[s] = (__half*)(base + 2 * A_BYTES + B_BYTES);
    }

    const int t    = threadIdx.x;
    const int lane = t & 31;
    const int wid  = t >> 5;
    const int wm   = wid & 1;
    const int wn   = wid >> 1;            // 0..WN-1
    const int wn_off = wn * 64;
    const int m0   = blockIdx.x * TBM;
    const int n0   = blockIdx.y * TBN;
    const int kofs = blockIdx.z * kslice_kt * TBK;

    float acc[4][8][4];
#pragma unroll
    for (int i = 0; i < 4; i++)
#pragma unroll
        for (int j = 0; j < 8; j++)
#pragma unroll
            for (int q = 0; q < 4; q++) acc[i][j][q] = 0.f;

    auto load_stage = [&](int s, int kt) {
        const int k0 = kofs + kt * TBK;
#pragma unroll
        for (int i = 0; i < 512 / NTHREADS; i++) {   // A: 512 x 16B pairs
            int idx = t + i * NTHREADS;
            int row = idx >> 2, seg = idx & 3;
            int so = row * ASTR + seg * 8;
            size_t go = (size_t)(m0 + row) * lda + k0 + seg * 8;
            cp16(&sAh[s][so], &Ah[go]);
            cp16(&sAl[s][so], &Al[go]);
        }
#pragma unroll
        for (int i = 0; i < 4; i++) {                // B: 32 rows x WN*8 segs
            int idx = t + i * NTHREADS;
            int row = idx / (WN * 8);
            int seg = idx % (WN * 8);
            int so = row * BSTR + seg * 8;
            size_t go = (size_t)(k0 + row) * ldb + n0 + seg * 8;
            cp16(&sBh[s][so], &Bh[go]);
            if (NPROD == 3) cp16(&sBl[s][so], &Bl[go]);
        }
        asm volatile("cp.async.commit_group;\n");
    };

    load_stage(0, 0);
    if (KT > 1) load_stage(1, 1);

    int slot = 0;
    for (int kt = 0; kt < KT; kt++) {
        if (kt < KT - 1) asm volatile("cp.async.wait_group 1;\n" ::: "memory");
        else             asm volatile("cp.async.wait_group 0;\n" ::: "memory");
        __syncthreads();
        if (kt + 2 < KT) {
            int ns = slot + 2; if (ns >= NSTG) ns -= NSTG;
            load_stage(ns, kt + 2);
        }

#pragma unroll
        for (int ks = 0; ks < 2; ks++) {
            uint32_t afh[4][4], afl[4][4];
#pragma unroll
            for (int mt = 0; mt < 4; mt++) {
                int r = wm * 64 + mt * 16 + (lane & 15);
                int c = ks * 16 + ((lane >> 4) << 3);
                ldsm_x4(afh[mt], &sAh[slot][r * ASTR + c]);
                ldsm_x4(afl[mt], &sAl[slot][r * ASTR + c]);
            }
            uint32_t bfh[8][2], bfl[8][2];
#pragma unroll
            for (int np = 0; np < 4; np++) {
                int r = ks * 16 + (lane & 15);
                int c = wn_off + np * 16 + ((lane >> 4) << 3);
                uint32_t rh[4];
                ldsm_x4_t(rh, &sBh[slot][r * BSTR + c]);
                bfh[np * 2][0] = rh[0]; bfh[np * 2][1] = rh[1];
                bfh[np * 2 + 1][0] = rh[2]; bfh[np * 2 + 1][1] = rh[3];
                if (NPROD == 3) {
                    uint32_t rl[4];
                    ldsm_x4_t(rl, &sBl[slot][r * BSTR + c]);
                    bfl[np * 2][0] = rl[0]; bfl[np * 2][1] = rl[1];
                    bfl[np * 2 + 1][0] = rl[2]; bfl[np * 2 + 1][1] = rl[3];
                }
            }
#pragma unroll
            for (int mt = 0; mt < 4; mt++)
#pragma unroll
                for (int nt = 0; nt < 8; nt++)
                    mma16816(acc[mt][nt], afh[mt], bfh[nt]);   // hh
#pragma unroll
            for (int mt = 0; mt < 4; mt++)
#pragma unroll
                for (int nt = 0; nt < 8; nt++)
                    mma16816(acc[mt][nt], afl[mt], bfh[nt]);   // lh
            if (NPROD == 3) {
#pragma unroll
                for (int mt = 0; mt < 4; mt++)
#pragma unroll
                    for (int nt = 0; nt < 8; nt++)
                        mma16816(acc[mt][nt], afh[mt], bfl[nt]);  // hl
            }
        }
        slot++; if (slot >= NSTG) slot -= NSTG;
    }

    float* Cz = C + (size_t)blockIdx.z * ((size_t)BATCH * ldc);
#pragma unroll
    for (int mt = 0; mt < 4; mt++) {
#pragma unroll
        for (int nt = 0; nt < 8; nt++) {
            int col = n0 + wn_off + nt * 8 + (lane & 3) * 2;
            if (col >= Nreal) continue;
            float b0 = 0.f, b1 = 0.f;
            if (ACT != ACT_RAW) { b0 = bias[col]; b1 = bias[col + 1]; }
#pragma unroll
            for (int h = 0; h < 2; h++) {
                int row = m0 + wm * 64 + mt * 16 + (lane >> 2) + h * 8;
                float v0 = acc[mt][nt][2 * h + 0] + b0;
                float v1 = acc[mt][nt][2 * h + 1] + b1;
                if (ACT == ACT_TANH) { v0 = tanhf(v0); v1 = tanhf(v1); }
                *(float2*)&Cz[(size_t)row * ldc + col] = make_float2(v0, v1);
            }
        }
    }
}

// ---------------- coalesced split-K combine -> elu -> fp16 hi/lo -----------
template <int NS>
__global__ void reduce_elu_split2(const float* __restrict__ ws, int ldw,
                                  const float* __restrict__ bias,
                                  __half* __restrict__ hi,
                                  __half* __restrict__ lo,
                                  int Nreal, int Npad)
{
    int m = blockIdx.x;
    int n = threadIdx.x * 4;
    if (n >= Npad) return;
    float v[4] = {0.f, 0.f, 0.f, 0.f};
    if (n < Nreal) {
        float4 b4 = *(const float4*)&bias[n];
        v[0] = b4.x; v[1] = b4.y; v[2] = b4.z; v[3] = b4.w;
        const float* row = ws + (size_t)m * ldw + n;
#pragma unroll
        for (int z = 0; z < NS; z++) {
            float4 w4 = *(const float4*)&row[(size_t)z * BATCH * ldw];
            v[0] += w4.x; v[1] += w4.y; v[2] += w4.z; v[3] += w4.w;
        }
#pragma unroll
        for (int i = 0; i < 4; i++) v[i] = v[i] > 0.f ? v[i] : expm1f(v[i]);
    }
    store_split4(hi, lo, (size_t)m * Npad + n, v);
}

// ---------------- fused latent chain ----------------------------------------
__global__ void __launch_bounds__(256)
latent_chain_kernel(const float* __restrict__ ws2, int ldw,
                    const float* __restrict__ b2,
                    const float* __restrict__ lw, const float* __restrict__ lb,
                    const float* __restrict__ W,
                    const float* __restrict__ noise,
                    const float* __restrict__ dw1, const float* __restrict__ db1,
                    float* __restrict__ lv_o, float* __restrict__ z_o,
                    float* __restrict__ bz_o, float* __restrict__ bm_o,
                    __half* __restrict__ g1h, __half* __restrict__ g1l)
{
    if (blockIdx.x == gridDim.x - 1) {
        int t = threadIdx.x;
        int i = t >> 4, j = t & 15;
        bm_o[t] = (j > i) ? W[t] * (float)(j - i) : 0.f;
        return;
    }

    const int lane = threadIdx.x & 31;
    const int b = blockIdx.x * 8 + (threadIdx.x >> 5);

    float acc[D];
#pragma unroll
    for (int j = 0; j < D; j++) acc[j] = 0.f;

#pragma unroll
    for (int tt = 0; tt < 10; tt++) {
        int k = lane + tt * 32;
        if (k < H2) {
            size_t o = (size_t)b * ldw + k;
            float hv = b2[k];
#pragma unroll
            for (int z = 0; z < 3; z++)
                hv += ws2[(size_t)z * BATCH * ldw + o];
            hv = hv > 0.f ? hv : expm1f(hv);
#pragma unroll
            for (int j4 = 0; j4 < 4; j4++) {
                float4 w = *(const float4*)&lw[(size_t)k * D + j4 * 4];
                acc[j4 * 4 + 0] = fmaf(hv, w.x, acc[j4 * 4 + 0]);
                acc[j4 * 4 + 1] = fmaf(hv, w.y, acc[j4 * 4 + 1]);
                acc[j4 * 4 + 2] = fmaf(hv, w.z, acc[j4 * 4 + 2]);
                acc[j4 * 4 + 3] = fmaf(hv, w.w, acc[j4 * 4 + 3]);
            }
        }
    }
#pragma unroll
    for (int off = 16; off > 0; off >>= 1)
#pragma unroll
        for (int j = 0; j < D; j++)
            acc[j] += __shfl_xor_sync(0xFFFFFFFF, acc[j], off);

#pragma unroll
    for (int j = 0; j < D; j++) acc[j] += lb[j];

    float eps[D], zz[D], bz[D];
#pragma unroll
    for (int j = 0; j < D; j++)
        eps[j] = expf(0.5f * acc[j]) * noise[(size_t)b * D + j];
#pragma unroll
    for (int j = 0; j < D; j++) {
        float s = 0.f;
#pragma unroll
        for (int i = 0; i < D; i++)
            if (i < j) s = fmaf(zz[i], W[i * D + j] * (float)(j - i), s);
        bz[j] = s;
        zz[j] = eps[j] + s;
    }
    if (lane < D) {
        lv_o[(size_t)b * D + lane] = acc[lane];
        z_o [(size_t)b * D + lane] = zz[lane];
        bz_o[(size_t)b * D + lane] = bz[lane];
    }

#pragma unroll
    for (int tt = 0; tt < H2K / 32; tt++) {
        int c = lane + tt * 32;
        float v = 0.f;
        if (c < H2) {
            v = db1[c];
#pragma unroll
            for (int k = 0; k < D; k++)
                v = fmaf(zz[k], dw1[k * H2 + c], v);
            v = v > 0.f ? v : expm1f(v);
        }
        __half h = __float2half_rn(v);
        size_t o = (size_t)b * H2K + c;
        g1h[o] = h;
        g1l[o] = __float2half_rn(v - __half2float(h));
    }
}

// ---------------- launch -----------------------------------------------------
extern "C" void kernel_launch(void* const* d_in, const int* in_sizes, int n_in,
                              void* d_out, int out_size)
{
    (void)in_sizes; (void)n_in; (void)out_size;

    const float* x        = (const float*)d_in[0];
    const float* noise    = (const float*)d_in[1];
    const float* enc_w1   = (const float*)d_in[2];
    const float* enc_b1   = (const float*)d_in[3];
    const float* enc_w2   = (const float*)d_in[4];
    const float* enc_b2   = (const float*)d_in[5];
    const float* logvar_w = (const float*)d_in[6];
    const float* logvar_b = (const float*)d_in[7];
    const float* W        = (const float*)d_in[8];
    const float* dec_w1   = (const float*)d_in[9];
    const float* dec_b1   = (const float*)d_in[10];
    const float* dec_w2   = (const float*)d_in[11];
    const float* dec_b2   = (const float*)d_in[12];
    const float* dec_w3   = (const float*)d_in[13];
    const float* dec_b3   = (const float*)d_in[14];

    float* out  = (float*)d_out;
    float* z_o  = out;
    float* lv_o = out + BATCH * D;
    float* bz_o = out + 2 * BATCH * D;
    float* bm_o = out + 3 * BATCH * D;
    float* xh_o = out + 3 * BATCH * D + D * D;

    float* ws;
    cudaGetSymbolAddress((void**)&ws, g_ws);
    __half *xh, *xl, *w1h, *h1h, *h1l, *w2h, *w2l;
    __half *g1h, *g1l, *dw2h, *dw2l, *g2h, *g2l, *w3h, *w3l;
    cudaGetSymbolAddress((void**)&xh,   g_xh);
    cudaGetSymbolAddress((void**)&xl,   g_xl);
    cudaGetSymbolAddress((void**)&w1h,  g_w1h);
    cudaGetSymbolAddress((void**)&h1h,  g_h1h);
    cudaGetSymbolAddress((void**)&h1l,  g_h1l);
    cudaGetSymbolAddress((void**)&w2h,  g_w2h);
    cudaGetSymbolAddress((void**)&w2l,  g_w2l);
    cudaGetSymbolAddress((void**)&g1h,  g_g1h);
    cudaGetSymbolAddress((void**)&g1l,  g_g1l);
    cudaGetSymbolAddress((void**)&dw2h, g_dw2h);
    cudaGetSymbolAddress((void**)&dw2l, g_dw2l);
    cudaGetSymbolAddress((void**)&g2h,  g_g2h);
    cudaGetSymbolAddress((void**)&g2l,  g_g2l);
    cudaGetSymbolAddress((void**)&w3h,  g_w3h);
    cudaGetSymbolAddress((void**)&w3l,  g_w3l);

    cudaFuncSetAttribute((const void*)mma_gemm_big<ACT_RAW, 2, 4>,
                         cudaFuncAttributeMaxDynamicSharedMemorySize, SMEM_OF(4));
    cudaFuncSetAttribute((const void*)mma_gemm_big<ACT_TANH, 3, 4>,
                         cudaFuncAttributeMaxDynamicSharedMemorySize, SMEM_OF(4));
    cudaFuncSetAttribute((const void*)mma_gemm_big<ACT_RAW, 3, 2>,
                         cudaFuncAttributeMaxDynamicSharedMemorySize, SMEM_OF(2));

    static cudaStream_t s1 = nullptr;
    static cudaEvent_t ev_fork = nullptr, ev_join = nullptr;
    if (s1 == nullptr) {
        cudaStreamCreateWithFlags(&s1, cudaStreamNonBlocking);
        cudaEventCreateWithFlags(&ev_fork, cudaEventDisableTiming);
        cudaEventCreateWithFlags(&ev_join, cudaEventDisableTiming);
    }

    dim3 blk(256);

    // ---- fork: prep_rest on s1 (concurrent with enc1 chain)
    cudaEventRecord(ev_fork, 0);
    cudaStreamWaitEvent(s1, ev_fork, 0);
    prep_rest<<<PR_W3, blk, 0, s1>>>(enc_w2, w2h, w2l, dec_w2, dw2h, dw2l,
                                     dec_w3, w3h, w3l);
    cudaEventRecord(ev_join, s1);

    // ---- main: x split + w1 conv
    prep_main<<<PM_W1, blk>>>(x, xh, xl, enc_w1, w1h);

    // ---- enc1 (2-product, WN=4: CTA 128x256, split-K=4) + combine
    {
        int kt = IMG / (4 * TBK);                 // 216
        mma_gemm_big<ACT_RAW, 2, 4><<<dim3(BATCH / TBM, W1N / 256, 4), 256, SMEM_OF(4)>>>(
            xh, xl, IMG, w1h, nullptr, W1N, nullptr, ws, W1N, W1N, kt, kt);
    }
    reduce_elu_split2<4><<<BATCH, H1K / 4>>>(ws, W1N, enc_b1, h1h, h1l, H1, H1K);

    // ---- join before enc2
    cudaStreamWaitEvent(0, ev_join, 0);

    // ---- enc2 (3-product, WN=2, 3 K-slices of 10 kt)
    mma_gemm_big<ACT_RAW, 3, 2><<<dim3(BATCH / TBM, H2N / 128, 3), 128, SMEM_OF(2)>>>(
        h1h, h1l, H1K, w2h, w2l, H2N, nullptr, ws, H2N, H2N, 10, 10);

    // ---- fused latent chain
    latent_chain_kernel<<<BATCH / 8 + 1, blk>>>(
        ws, H2N, enc_b2, logvar_w, logvar_b, W, noise, dec_w1, dec_b1,
        lv_o, z_o, bz_o, bm_o, g1h, g1l);

    // ---- dec2 (3-product, WN=2, 2 K-slices of 5 kt) + combine
    mma_gemm_big<ACT_RAW, 3, 2><<<dim3(BATCH / TBM, H2N / 128, 2), 128, SMEM_OF(2)>>>(
        g1h, g1l, H2K, dw2h, dw2l, H2N, nullptr, ws, H2N, H2N, 5, 5);
    reduce_elu_split2<2><<<BATCH, H2K / 4>>>(ws, H2N, dec_b2, g2h, g2l, H2, H2K);

    // ---- dec3 (3-product, WN=4: CTA 128x256, tanh)
    mma_gemm_big<ACT_TANH, 3, 4><<<dim3(BATCH / TBM, IMG / 256, 1), 256, SMEM_OF(4)>>>(
        g2h, g2l, H2K, w3h, w3l, IMG, dec_b3, xh_o, IMG, IMG, H2K / TBK, H2K / TBK);
}

// round 16
// speedup vs baseline: 1.1511x; 1.1511x over previous
#include <cuda_runtime.h>
#include <cuda_fp16.h>
#include <math.h>
#include <stdint.h>

// ---------------------------------------------------------------------------
// VAE forward. Round 16: consolidation — exact restore of the R8 optimum
// (610.8us). fp16 hi/lo splits; enc1 2-product (A split, B single fp16);
// enc2/dec2/dec3 3-product. 128x128 CTA / 64x64 warp tiles / 3-stage cp.async
// / 2 CTAs/SM. Five structural probes (R11,R13,R14,R15) confirmed this config
// sits at the sm_103a reg-path HMMA ceiling (~305 TF/s).
// ---------------------------------------------------------------------------

#define BATCH 1024
#define IMG   27648
#define H1    900
#define H2    300
#define D     16

#define W1N 1024           // enc1 N padded
#define H1K 960            // h1 K padded (enc2 A)
#define H2N 384            // enc2/dec2 N padded
#define H2K 320            // g1/g2 K padded (dec2/dec3 A)

enum { ACT_TANH = 2, ACT_RAW = 3 };

// ---------------- scratch ----------------------------------------------------
__device__ float g_ws[4 * BATCH * W1N];          // split-K partials (reused)

__device__ __align__(16) __half g_xh[(size_t)BATCH * IMG];
__device__ __align__(16) __half g_xl[(size_t)BATCH * IMG];
__device__ __align__(16) __half g_w1h[(size_t)IMG * W1N];
__device__ __align__(16) __half g_h1h[(size_t)BATCH * H1K];
__device__ __align__(16) __half g_h1l[(size_t)BATCH * H1K];
__device__ __align__(16) __half g_w2h[(size_t)H1K * H2N];
__device__ __align__(16) __half g_w2l[(size_t)H1K * H2N];
__device__ __align__(16) __half g_g1h[(size_t)BATCH * H2K];
__device__ __align__(16) __half g_g1l[(size_t)BATCH * H2K];
__device__ __align__(16) __half g_dw2h[(size_t)H2K * H2N];
__device__ __align__(16) __half g_dw2l[(size_t)H2K * H2N];
__device__ __align__(16) __half g_g2h[(size_t)BATCH * H2K];
__device__ __align__(16) __half g_g2l[(size_t)BATCH * H2K];
__device__ __align__(16) __half g_w3h[(size_t)H2K * IMG];
__device__ __align__(16) __half g_w3l[(size_t)H2K * IMG];

// ---------------- fp32 -> fp16 hi/lo split (zero-padded) -------------------
__global__ void split_half_v4(const float* __restrict__ src,
                              __half* __restrict__ hi,
                              __half* __restrict__ lo,
                              int src_rows, int src_cols, int dst_cols)
{
    int c = (blockIdx.x * 256 + threadIdx.x) * 4;
    int r = blockIdx.y;
    if (c >= dst_cols) return;
    float v[4];
    if (r < src_rows && c + 3 < src_cols) {
        float4 f = *(const float4*)&src[(size_t)r * src_cols + c];
        v[0] = f.x; v[1] = f.y; v[2] = f.z; v[3] = f.w;
    } else {
#pragma unroll
        for (int i = 0; i < 4; i++)
            v[i] = (r < src_rows && c + i < src_cols)
                 ? src[(size_t)r * src_cols + c + i] : 0.f;
    }
    __half h4[4], l4[4];
#pragma unroll
    for (int i = 0; i < 4; i++) {
        h4[i] = __float2half_rn(v[i]);
        l4[i] = __float2half_rn(v[i] - __half2float(h4[i]));
    }
    size_t o = (size_t)r * dst_cols + c;
    *(uint64_t*)&hi[o] = *(uint64_t*)h4;
    *(uint64_t*)&lo[o] = *(uint64_t*)l4;
}

// fp32 -> single fp16 (zero-padded)
__global__ void conv_half_v4(const float* __restrict__ src,
                             __half* __restrict__ hi,
                             int src_rows, int src_cols, int dst_cols)
{
    int c = (blockIdx.x * 256 + threadIdx.x) * 4;
    int r = blockIdx.y;
    if (c >= dst_cols) return;
    float v[4];
    if (r < src_rows && c + 3 < src_cols) {
        float4 f = *(const float4*)&src[(size_t)r * src_cols + c];
        v[0] = f.x; v[1] = f.y; v[2] = f.z; v[3] = f.w;
    } else {
#pragma unroll
        for (int i = 0; i < 4; i++)
            v[i] = (r < src_rows && c + i < src_cols)
                 ? src[(size_t)r * src_cols + c + i] : 0.f;
    }
    __half h4[4];
#pragma unroll
    for (int i = 0; i < 4; i++) h4[i] = __float2half_rn(v[i]);
    *(uint64_t*)&hi[(size_t)r * dst_cols + c] = *(uint64_t*)h4;
}

// ---------------- tensor-core GEMM (fp16, 64x64 warp tiles) ----------------
#define TBM 128
#define TBN 128
#define TBK 32
#define ASTR 40
#define BSTR 136
#define NSTG 3

#define A_BYTES (TBM * ASTR * 2)
#define B_BYTES (TBK * BSTR * 2)
#define STAGE_BYTES (2 * A_BYTES + 2 * B_BYTES)
#define SMEM_BYTES (NSTG * STAGE_BYTES)

__device__ __forceinline__ void cp16(void* s, const void* g)
{
    uint32_t sa = (uint32_t)__cvta_generic_to_shared(s);
    asm volatile("cp.async.cg.shared.global [%0], [%1], 16;\n" :: "r"(sa), "l"(g));
}

__device__ __forceinline__ void ldsm_x4(uint32_t* r, const void* p)
{
    uint32_t a = (uint32_t)__cvta_generic_to_shared(p);
    asm volatile("ldmatrix.sync.aligned.m8n8.x4.shared.b16 {%0,%1,%2,%3}, [%4];\n"
                 : "=r"(r[0]), "=r"(r[1]), "=r"(r[2]), "=r"(r[3]) : "r"(a));
}

__device__ __forceinline__ void ldsm_x4_t(uint32_t* r, const void* p)
{
    uint32_t a = (uint32_t)__cvta_generic_to_shared(p);
    asm volatile("ldmatrix.sync.aligned.m8n8.x4.trans.shared.b16 {%0,%1,%2,%3}, [%4];\n"
                 : "=r"(r[0]), "=r"(r[1]), "=r"(r[2]), "=r"(r[3]) : "r"(a));
}

__device__ __forceinline__ void mma16816(float* c, const uint32_t* a, const uint32_t* b)
{
    asm volatile(
        "mma.sync.aligned.m16n8k16.row.col.f32.f16.f16.f32 "
        "{%0,%1,%2,%3}, {%4,%5,%6,%7}, {%8,%9}, {%0,%1,%2,%3};\n"
        : "+f"(c[0]), "+f"(c[1]), "+f"(c[2]), "+f"(c[3])
        : "r"(a[0]), "r"(a[1]), "r"(a[2]), "r"(a[3]), "r"(b[0]), "r"(b[1]));
}

// NPROD==2: C = Ah@Bh + Al@Bh            (A split, B single)
// NPROD==3: C = Ah@Bh + Al@Bh + Ah@Bl    (both split, residual Al@Bl dropped)
template <int ACT, int NPROD>
__global__ void __launch_bounds__(128, 2)
mma_gemm_big(const __half* __restrict__ Ah, const __half* __restrict__ Al,
             int lda,
             const __half* __restrict__ Bh, const __half* __restrict__ Bl,
             int ldb,
             const float* __restrict__ bias, float* __restrict__ C, int ldc,
             int Nreal, int KT, int kslice_kt)
{
    extern __shared__ char smem[];
    __half *sAh[NSTG], *sAl[NSTG], *sBh[NSTG], *sBl[NSTG];
#pragma unroll
    for (int s = 0; s < NSTG; s++) {
        char* base = smem + s * STAGE_BYTES;
        sAh[s] = (__half*)(base);
        sAl[s] = (__half*)(base + A_BYTES);
        sBh[s] = (__half*)(base + 2 * A_BYTES);
        sBl[s] = (__half*)(base + 2 * A_BYTES + B_BYTES);
    }

    const int t    = threadIdx.x;
    const int lane = t & 31;
    const int wid  = t >> 5;
    const int wm   = wid & 1;
    const int wn   = wid >> 1;
    const int m0   = blockIdx.y * TBM;
    const int n0   = blockIdx.x * TBN;
    const int kofs = blockIdx.z * kslice_kt * TBK;

    float acc[4][8][4];
#pragma unroll
    for (int i = 0; i < 4; i++)
#pragma unroll
        for (int j = 0; j < 8; j++)
#pragma unroll
            for (int q = 0; q < 4; q++) acc[i][j][q] = 0.f;

    auto load_stage = [&](int s, int kt) {
        const int k0 = kofs + kt * TBK;
#pragma unroll
        for (int i = 0; i < 4; i++) {
            int idx = t + i * 128;
            int row = idx >> 2, seg = idx & 3;
            int so = row * ASTR + seg * 8;
            size_t go = (size_t)(m0 + row) * lda + k0 + seg * 8;
            cp16(&sAh[s][so], &Ah[go]);
            cp16(&sAl[s][so], &Al[go]);
        }
#pragma unroll
        for (int i = 0; i < 4; i++) {
            int idx = t + i * 128;
            int row = idx >> 4, seg = idx & 15;
            int so = row * BSTR + seg * 8;
            size_t go = (size_t)(k0 + row) * ldb + n0 + seg * 8;
            cp16(&sBh[s][so], &Bh[go]);
            if (NPROD == 3) cp16(&sBl[s][so], &Bl[go]);
        }
        asm volatile("cp.async.commit_group;\n");
    };

    load_stage(0, 0);
    if (KT > 1) load_stage(1, 1);

    int slot = 0;
    for (int kt = 0; kt < KT; kt++) {
        if (kt < KT - 1) asm volatile("cp.async.wait_group 1;\n" ::: "memory");
        else             asm volatile("cp.async.wait_group 0;\n" ::: "memory");
        __syncthreads();
        if (kt + 2 < KT) {
            int ns = slot + 2; if (ns >= NSTG) ns -= NSTG;
            load_stage(ns, kt + 2);
        }

#pragma unroll
        for (int ks = 0; ks < 2; ks++) {
            uint32_t afh[4][4], afl[4][4];
#pragma unroll
            for (int mt = 0; mt < 4; mt++) {
                int r = wm * 64 + mt * 16 + (lane & 15);
                int c = ks * 16 + ((lane >> 4) << 3);
                ldsm_x4(afh[mt], &sAh[slot][r * ASTR + c]);
                ldsm_x4(afl[mt], &sAl[slot][r * ASTR + c]);
            }
            uint32_t bfh[8][2], bfl[8][2];
#pragma unroll
            for (int np = 0; np < 4; np++) {
                int r = ks * 16 + (lane & 15);
                int c = wn * 64 + np * 16 + ((lane >> 4) << 3);
                uint32_t rh[4];
                ldsm_x4_t(rh, &sBh[slot][r * BSTR + c]);
                bfh[np * 2][0] = rh[0]; bfh[np * 2][1] = rh[1];
                bfh[np * 2 + 1][0] = rh[2]; bfh[np * 2 + 1][1] = rh[3];
                if (NPROD == 3) {
                    uint32_t rl[4];
                    ldsm_x4_t(rl, &sBl[slot][r * BSTR + c]);
                    bfl[np * 2][0] = rl[0]; bfl[np * 2][1] = rl[1];
                    bfl[np * 2 + 1][0] = rl[2]; bfl[np * 2 + 1][1] = rl[3];
                }
            }
#pragma unroll
            for (int mt = 0; mt < 4; mt++)
#pragma unroll
                for (int nt = 0; nt < 8; nt++) {
                    mma16816(acc[mt][nt], afh[mt], bfh[nt]);   // hh
                    mma16816(acc[mt][nt], afl[mt], bfh[nt]);   // lh
                    if (NPROD == 3)
                        mma16816(acc[mt][nt], afh[mt], bfl[nt]);  // hl
                }
        }
        slot++; if (slot >= NSTG) slot -= NSTG;
    }

    float* Cz = C + (size_t)blockIdx.z * ((size_t)BATCH * ldc);
#pragma unroll
    for (int mt = 0; mt < 4; mt++) {
#pragma unroll
        for (int nt = 0; nt < 8; nt++) {
            int col = n0 + wn * 64 + nt * 8 + (lane & 3) * 2;
            if (col >= Nreal) continue;
            float b0 = 0.f, b1 = 0.f;
            if (ACT != ACT_RAW) { b0 = bias[col]; b1 = bias[col + 1]; }
#pragma unroll
            for (int h = 0; h < 2; h++) {
                int row = m0 + wm * 64 + mt * 16 + (lane >> 2) + h * 8;
                float v0 = acc[mt][nt][2 * h + 0] + b0;
                float v1 = acc[mt][nt][2 * h + 1] + b1;
                if (ACT == ACT_TANH) { v0 = tanhf(v0); v1 = tanhf(v1); }
                *(float2*)&Cz[(size_t)row * ldc + col] = make_float2(v0, v1);
            }
        }
    }
}

// ---------------- split-K combine -> elu -> fp16 hi/lo ---------------------
template <int NS>
__global__ void reduce_elu_split(const float* __restrict__ ws, int ldw,
                                 const float* __restrict__ bias,
                                 __half* __restrict__ hi,
                                 __half* __restrict__ lo,
                                 int Nreal, int Npad, int total)
{
    int i = blockIdx.x * 256 + threadIdx.x;
    if (i >= total) return;
    int m = i / Npad, n = i - m * Npad;
    float v = 0.f;
    if (n < Nreal) {
        size_t o = (size_t)m * ldw + n;
        v = bias[n];
#pragma unroll
        for (int z = 0; z < NS; z++)
            v += ws[(size_t)z * BATCH * ldw + o];
        v = v > 0.f ? v : expm1f(v);
    }
    __half h = __float2half_rn(v);
    hi[i] = h;
    lo[i] = __float2half_rn(v - __half2float(h));
}

// ---------------- fused latent chain ----------------------------------------
// h2 = elu(sum_{z<3} ws2[z] + b2); logvar = h2@lw + lb; eps; triangular solve;
// g1 = elu(z @ dw1 + db1) emitted as fp16 hi/lo; last block writes Bmat.
__global__ void __launch_bounds__(256)
latent_chain_kernel(const float* __restrict__ ws2, int ldw,
                    const float* __restrict__ b2,
                    const float* __restrict__ lw, const float* __restrict__ lb,
                    const float* __restrict__ W,
                    const float* __restrict__ noise,
                    const float* __restrict__ dw1, const float* __restrict__ db1,
                    float* __restrict__ lv_o, float* __restrict__ z_o,
                    float* __restrict__ bz_o, float* __restrict__ bm_o,
                    __half* __restrict__ g1h, __half* __restrict__ g1l)
{
    if (blockIdx.x == gridDim.x - 1) {        // Bmat block
        int t = threadIdx.x;
        int i = t >> 4, j = t & 15;
        bm_o[t] = (j > i) ? W[t] * (float)(j - i) : 0.f;
        return;
    }

    const int lane = threadIdx.x & 31;
    const int b = blockIdx.x * 8 + (threadIdx.x >> 5);

    float acc[D];
#pragma unroll
    for (int j = 0; j < D; j++) acc[j] = 0.f;

#pragma unroll
    for (int tt = 0; tt < 10; tt++) {
        int k = lane + tt * 32;
        if (k < H2) {
            size_t o = (size_t)b * ldw + k;
            float hv = b2[k];
#pragma unroll
            for (int z = 0; z < 3; z++)
                hv += ws2[(size_t)z * BATCH * ldw + o];
            hv = hv > 0.f ? hv : expm1f(hv);
#pragma unroll
            for (int j4 = 0; j4 < 4; j4++) {
                float4 w = *(const float4*)&lw[(size_t)k * D + j4 * 4];
                acc[j4 * 4 + 0] = fmaf(hv, w.x, acc[j4 * 4 + 0]);
                acc[j4 * 4 + 1] = fmaf(hv, w.y, acc[j4 * 4 + 1]);
                acc[j4 * 4 + 2] = fmaf(hv, w.z, acc[j4 * 4 + 2]);
                acc[j4 * 4 + 3] = fmaf(hv, w.w, acc[j4 * 4 + 3]);
            }
        }
    }
#pragma unroll
    for (int off = 16; off > 0; off >>= 1)
#pragma unroll
        for (int j = 0; j < D; j++)
            acc[j] += __shfl_xor_sync(0xFFFFFFFF, acc[j], off);

#pragma unroll
    for (int j = 0; j < D; j++) acc[j] += lb[j];

    float eps[D], zz[D], bz[D];
#pragma unroll
    for (int j = 0; j < D; j++)
        eps[j] = expf(0.5f * acc[j]) * noise[(size_t)b * D + j];
#pragma unroll
    for (int j = 0; j < D; j++) {
        float s = 0.f;
#pragma unroll
        for (int i = 0; i < D; i++)
            if (i < j) s = fmaf(zz[i], W[i * D + j] * (float)(j - i), s);
        bz[j] = s;
        zz[j] = eps[j] + s;
    }
    if (lane < D) {
        lv_o[(size_t)b * D + lane] = acc[lane];
        z_o [(size_t)b * D + lane] = zz[lane];
        bz_o[(size_t)b * D + lane] = bz[lane];
    }

    // dec1: g1 = elu(z @ dw1 + db1), padded to H2K, fp16 hi/lo
#pragma unroll
    for (int tt = 0; tt < H2K / 32; tt++) {
        int c = lane + tt * 32;
        float v = 0.f;
        if (c < H2) {
            v = db1[c];
#pragma unroll
            for (int k = 0; k < D; k++)
                v = fmaf(zz[k], dw1[k * H2 + c], v);
            v = v > 0.f ? v : expm1f(v);
        }
        __half h = __float2half_rn(v);
        size_t o = (size_t)b * H2K + c;
        g1h[o] = h;
        g1l[o] = __float2half_rn(v - __half2float(h));
    }
}

// ---------------- launch -----------------------------------------------------
extern "C" void kernel_launch(void* const* d_in, const int* in_sizes, int n_in,
                              void* d_out, int out_size)
{
    (void)in_sizes; (void)n_in; (void)out_size;

    const float* x        = (const float*)d_in[0];
    const float* noise    = (const float*)d_in[1];
    const float* enc_w1   = (const float*)d_in[2];
    const float* enc_b1   = (const float*)d_in[3];
    const float* enc_w2   = (const float*)d_in[4];
    const float* enc_b2   = (const float*)d_in[5];
    const float* logvar_w = (const float*)d_in[6];
    const float* logvar_b = (const float*)d_in[7];
    const float* W        = (const float*)d_in[8];
    const float* dec_w1   = (const float*)d_in[9];
    const float* dec_b1   = (const float*)d_in[10];
    const float* dec_w2   = (const float*)d_in[11];
    const float* dec_b2   = (const float*)d_in[12];
    const float* dec_w3   = (const float*)d_in[13];
    const float* dec_b3   = (const float*)d_in[14];

    float* out  = (float*)d_out;
    float* z_o  = out;
    float* lv_o = out + BATCH * D;
    float* bz_o = out + 2 * BATCH * D;
    float* bm_o = out + 3 * BATCH * D;
    float* xh_o = out + 3 * BATCH * D + D * D;

    float* ws;
    cudaGetSymbolAddress((void**)&ws, g_ws);
    __half *xh, *xl, *w1h, *h1h, *h1l, *w2h, *w2l;
    __half *g1h, *g1l, *dw2h, *dw2l, *g2h, *g2l, *w3h, *w3l;
    cudaGetSymbolAddress((void**)&xh,   g_xh);
    cudaGetSymbolAddress((void**)&xl,   g_xl);
    cudaGetSymbolAddress((void**)&w1h,  g_w1h);
    cudaGetSymbolAddress((void**)&h1h,  g_h1h);
    cudaGetSymbolAddress((void**)&h1l,  g_h1l);
    cudaGetSymbolAddress((void**)&w2h,  g_w2h);
    cudaGetSymbolAddress((void**)&w2l,  g_w2l);
    cudaGetSymbolAddress((void**)&g1h,  g_g1h);
    cudaGetSymbolAddress((void**)&g1l,  g_g1l);
    cudaGetSymbolAddress((void**)&dw2h, g_dw2h);
    cudaGetSymbolAddress((void**)&dw2l, g_dw2l);
    cudaGetSymbolAddress((void**)&g2h,  g_g2h);
    cudaGetSymbolAddress((void**)&g2l,  g_g2l);
    cudaGetSymbolAddress((void**)&w3h,  g_w3h);
    cudaGetSymbolAddress((void**)&w3l,  g_w3l);

    cudaFuncSetAttribute((const void*)mma_gemm_big<ACT_RAW, 2>,
                         cudaFuncAttributeMaxDynamicSharedMemorySize, SMEM_BYTES);
    cudaFuncSetAttribute((const void*)mma_gemm_big<ACT_RAW, 3>,
                         cudaFuncAttributeMaxDynamicSharedMemorySize, SMEM_BYTES);
    cudaFuncSetAttribute((const void*)mma_gemm_big<ACT_TANH, 3>,
                         cudaFuncAttributeMaxDynamicSharedMemorySize, SMEM_BYTES);

    dim3 blk(256);

    // ---- operand prep
    split_half_v4<<<dim3(IMG / 1024, BATCH), blk>>>(x, xh, xl, BATCH, IMG, IMG);
    conv_half_v4<<<dim3(1, IMG), blk>>>(enc_w1, w1h, IMG, H1, W1N);
    split_half_v4<<<dim3(1, H1K), blk>>>(enc_w2, w2h, w2l, H1, H2, H2N);
    split_half_v4<<<dim3(1, H2K), blk>>>(dec_w2, dw2h, dw2l, H2, H2, H2N);
    split_half_v4<<<dim3(IMG / 1024, H2K), blk>>>(dec_w3, w3h, w3l, H2, IMG, IMG);

    // ---- enc1: 2-product, split-K=4
    {
        int kt = IMG / (4 * TBK);                 // 216
        mma_gemm_big<ACT_RAW, 2><<<dim3(W1N / TBN, BATCH / TBM, 4), 128, SMEM_BYTES>>>(
            xh, xl, IMG, w1h, nullptr, W1N, nullptr, ws, W1N, W1N, kt, kt);
    }
    reduce_elu_split<4><<<(BATCH * H1K + 255) / 256, blk>>>(
        ws, W1N, enc_b1, h1h, h1l, H1, H1K, BATCH * H1K);

    // ---- enc2: 3-product, 3 K-slices of 10 kt
    mma_gemm_big<ACT_RAW, 3><<<dim3(H2N / TBN, BATCH / TBM, 3), 128, SMEM_BYTES>>>(
        h1h, h1l, H1K, w2h, w2l, H2N, nullptr, ws, H2N, H2N, 10, 10);

    // ---- fused latent chain (h2 sum + logvar + solve + dec1 + Bmat)
    latent_chain_kernel<<<BATCH / 8 + 1, blk>>>(
        ws, H2N, enc_b2, logvar_w, logvar_b, W, noise, dec_w1, dec_b1,
        lv_o, z_o, bz_o, bm_o, g1h, g1l);

    // ---- dec2: 3-product, 2 K-slices of 5 kt
    mma_gemm_big<ACT_RAW, 3><<<dim3(H2N / TBN, BATCH / TBM, 2), 128, SMEM_BYTES>>>(
        g1h, g1l, H2K, dw2h, dw2l, H2N, nullptr, ws, H2N, H2N, 5, 5);
    reduce_elu_split<2><<<(BATCH * H2K + 255) / 256, blk>>>(
        ws, H2N, dec_b2, g2h, g2l, H2, H2K, BATCH * H2K);

    // ---- dec3: 3-product, tanh
    mma_gemm_big<ACT_TANH, 3><<<dim3(IMG / TBN, BATCH / TBM, 1), 128, SMEM_BYTES>>>(
        g2h, g2l, H2K, w3h, w3l, IMG, dec_b3, xh_o, IMG, IMG, H2K / TBK, H2K / TBK);
}

// round 17
// speedup vs baseline: 1.1531x; 1.0018x over previous
#include <cuda_runtime.h>
#include <cuda_fp16.h>
#include <math.h>
#include <stdint.h>

// ---------------------------------------------------------------------------
// VAE forward. Round 17: R8/R16 optimum + coalesced float4 reduce kernels
// (only component with a measured positive delta). fp16 hi/lo splits; enc1
// 2-product, enc2/dec2/dec3 3-product; 128x128 CTA / 64x64 warp tiles /
// 3-stage cp.async / 2 CTAs/SM — at the sm_103a reg-path HMMA ceiling.
// ---------------------------------------------------------------------------

#define BATCH 1024
#define IMG   27648
#define H1    900
#define H2    300
#define D     16

#define W1N 1024
#define H1K 960
#define H2N 384
#define H2K 320

enum { ACT_TANH = 2, ACT_RAW = 3 };

// ---------------- scratch ----------------------------------------------------
__device__ float g_ws[4 * BATCH * W1N];

__device__ __align__(16) __half g_xh[(size_t)BATCH * IMG];
__device__ __align__(16) __half g_xl[(size_t)BATCH * IMG];
__device__ __align__(16) __half g_w1h[(size_t)IMG * W1N];
__device__ __align__(16) __half g_h1h[(size_t)BATCH * H1K];
__device__ __align__(16) __half g_h1l[(size_t)BATCH * H1K];
__device__ __align__(16) __half g_w2h[(size_t)H1K * H2N];
__device__ __align__(16) __half g_w2l[(size_t)H1K * H2N];
__device__ __align__(16) __half g_g1h[(size_t)BATCH * H2K];
__device__ __align__(16) __half g_g1l[(size_t)BATCH * H2K];
__device__ __align__(16) __half g_dw2h[(size_t)H2K * H2N];
__device__ __align__(16) __half g_dw2l[(size_t)H2K * H2N];
__device__ __align__(16) __half g_g2h[(size_t)BATCH * H2K];
__device__ __align__(16) __half g_g2l[(size_t)BATCH * H2K];
__device__ __align__(16) __half g_w3h[(size_t)H2K * IMG];
__device__ __align__(16) __half g_w3l[(size_t)H2K * IMG];

// ---------------- element helpers -------------------------------------------
__device__ __forceinline__ void store_split4(__half* __restrict__ hi,
                                             __half* __restrict__ lo,
                                             size_t o, const float v[4])
{
    __half h4[4], l4[4];
#pragma unroll
    for (int i = 0; i < 4; i++) {
        h4[i] = __float2half_rn(v[i]);
        l4[i] = __float2half_rn(v[i] - __half2float(h4[i]));
    }
    *(uint64_t*)&hi[o] = *(uint64_t*)h4;
    *(uint64_t*)&lo[o] = *(uint64_t*)l4;
}

// ---------------- fp32 -> fp16 hi/lo split (zero-padded) -------------------
__global__ void split_half_v4(const float* __restrict__ src,
                              __half* __restrict__ hi,
                              __half* __restrict__ lo,
                              int src_rows, int src_cols, int dst_cols)
{
    int c = (blockIdx.x * 256 + threadIdx.x) * 4;
    int r = blockIdx.y;
    if (c >= dst_cols) return;
    float v[4];
    if (r < src_rows && c + 3 < src_cols) {
        float4 f = *(const float4*)&src[(size_t)r * src_cols + c];
        v[0] = f.x; v[1] = f.y; v[2] = f.z; v[3] = f.w;
    } else {
#pragma unroll
        for (int i = 0; i < 4; i++)
            v[i] = (r < src_rows && c + i < src_cols)
                 ? src[(size_t)r * src_cols + c + i] : 0.f;
    }
    store_split4(hi, lo, (size_t)r * dst_cols + c, v);
}

// fp32 -> single fp16 (zero-padded)
__global__ void conv_half_v4(const float* __restrict__ src,
                             __half* __restrict__ hi,
                             int src_rows, int src_cols, int dst_cols)
{
    int c = (blockIdx.x * 256 + threadIdx.x) * 4;
    int r = blockIdx.y;
    if (c >= dst_cols) return;
    float v[4];
    if (r < src_rows && c + 3 < src_cols) {
        float4 f = *(const float4*)&src[(size_t)r * src_cols + c];
        v[0] = f.x; v[1] = f.y; v[2] = f.z; v[3] = f.w;
    } else {
#pragma unroll
        for (int i = 0; i < 4; i++)
            v[i] = (r < src_rows && c + i < src_cols)
                 ? src[(size_t)r * src_cols + c + i] : 0.f;
    }
    __half h4[4];
#pragma unroll
    for (int i = 0; i < 4; i++) h4[i] = __float2half_rn(v[i]);
    *(uint64_t*)&hi[(size_t)r * dst_cols + c] = *(uint64_t*)h4;
}

// ---------------- tensor-core GEMM (fp16, 64x64 warp tiles) ----------------
#define TBM 128
#define TBN 128
#define TBK 32
#define ASTR 40
#define BSTR 136
#define NSTG 3

#define A_BYTES (TBM * ASTR * 2)
#define B_BYTES (TBK * BSTR * 2)
#define STAGE_BYTES (2 * A_BYTES + 2 * B_BYTES)
#define SMEM_BYTES (NSTG * STAGE_BYTES)

__device__ __forceinline__ void cp16(void* s, const void* g)
{
    uint32_t sa = (uint32_t)__cvta_generic_to_shared(s);
    asm volatile("cp.async.cg.shared.global [%0], [%1], 16;\n" :: "r"(sa), "l"(g));
}

__device__ __forceinline__ void ldsm_x4(uint32_t* r, const void* p)
{
    uint32_t a = (uint32_t)__cvta_generic_to_shared(p);
    asm volatile("ldmatrix.sync.aligned.m8n8.x4.shared.b16 {%0,%1,%2,%3}, [%4];\n"
                 : "=r"(r[0]), "=r"(r[1]), "=r"(r[2]), "=r"(r[3]) : "r"(a));
}

__device__ __forceinline__ void ldsm_x4_t(uint32_t* r, const void* p)
{
    uint32_t a = (uint32_t)__cvta_generic_to_shared(p);
    asm volatile("ldmatrix.sync.aligned.m8n8.x4.trans.shared.b16 {%0,%1,%2,%3}, [%4];\n"
                 : "=r"(r[0]), "=r"(r[1]), "=r"(r[2]), "=r"(r[3]) : "r"(a));
}

__device__ __forceinline__ void mma16816(float* c, const uint32_t* a, const uint32_t* b)
{
    asm volatile(
        "mma.sync.aligned.m16n8k16.row.col.f32.f16.f16.f32 "
        "{%0,%1,%2,%3}, {%4,%5,%6,%7}, {%8,%9}, {%0,%1,%2,%3};\n"
        : "+f"(c[0]), "+f"(c[1]), "+f"(c[2]), "+f"(c[3])
        : "r"(a[0]), "r"(a[1]), "r"(a[2]), "r"(a[3]), "r"(b[0]), "r"(b[1]));
}

// NPROD==2: C = Ah@Bh + Al@Bh ; NPROD==3: + Ah@Bl.
template <int ACT, int NPROD>
__global__ void __launch_bounds__(128, 2)
mma_gemm_big(const __half* __restrict__ Ah, const __half* __restrict__ Al,
             int lda,
             const __half* __restrict__ Bh, const __half* __restrict__ Bl,
             int ldb,
             const float* __restrict__ bias, float* __restrict__ C, int ldc,
             int Nreal, int KT, int kslice_kt)
{
    extern __shared__ char smem[];
    __half *sAh[NSTG], *sAl[NSTG], *sBh[NSTG], *sBl[NSTG];
#pragma unroll
    for (int s = 0; s < NSTG; s++) {
        char* base = smem + s * STAGE_BYTES;
        sAh[s] = (__half*)(base);
        sAl[s] = (__half*)(base + A_BYTES);
        sBh[s] = (__half*)(base + 2 * A_BYTES);
        sBl[s] = (__half*)(base + 2 * A_BYTES + B_BYTES);
    }

    const int t    = threadIdx.x;
    const int lane = t & 31;
    const int wid  = t >> 5;
    const int wm   = wid & 1;
    const int wn   = wid >> 1;
    const int m0   = blockIdx.y * TBM;
    const int n0   = blockIdx.x * TBN;
    const int kofs = blockIdx.z * kslice_kt * TBK;

    float acc[4][8][4];
#pragma unroll
    for (int i = 0; i < 4; i++)
#pragma unroll
        for (int j = 0; j < 8; j++)
#pragma unroll
            for (int q = 0; q < 4; q++) acc[i][j][q] = 0.f;

    auto load_stage = [&](int s, int kt) {
        const int k0 = kofs + kt * TBK;
#pragma unroll
        for (int i = 0; i < 4; i++) {
            int idx = t + i * 128;
            int row = idx >> 2, seg = idx & 3;
            int so = row * ASTR + seg * 8;
            size_t go = (size_t)(m0 + row) * lda + k0 + seg * 8;
            cp16(&sAh[s][so], &Ah[go]);
            cp16(&sAl[s][so], &Al[go]);
        }
#pragma unroll
        for (int i = 0; i < 4; i++) {
            int idx = t + i * 128;
            int row = idx >> 4, seg = idx & 15;
            int so = row * BSTR + seg * 8;
            size_t go = (size_t)(k0 + row) * ldb + n0 + seg * 8;
            cp16(&sBh[s][so], &Bh[go]);
            if (NPROD == 3) cp16(&sBl[s][so], &Bl[go]);
        }
        asm volatile("cp.async.commit_group;\n");
    };

    load_stage(0, 0);
    if (KT > 1) load_stage(1, 1);

    int slot = 0;
    for (int kt = 0; kt < KT; kt++) {
        if (kt < KT - 1) asm volatile("cp.async.wait_group 1;\n" ::: "memory");
        else             asm volatile("cp.async.wait_group 0;\n" ::: "memory");
        __syncthreads();
        if (kt + 2 < KT) {
            int ns = slot + 2; if (ns >= NSTG) ns -= NSTG;
            load_stage(ns, kt + 2);
        }

#pragma unroll
        for (int ks = 0; ks < 2; ks++) {
            uint32_t afh[4][4], afl[4][4];
#pragma unroll
            for (int mt = 0; mt < 4; mt++) {
                int r = wm * 64 + mt * 16 + (lane & 15);
                int c = ks * 16 + ((lane >> 4) << 3);
                ldsm_x4(afh[mt], &sAh[slot][r * ASTR + c]);
                ldsm_x4(afl[mt], &sAl[slot][r * ASTR + c]);
            }
            uint32_t bfh[8][2], bfl[8][2];
#pragma unroll
            for (int np = 0; np < 4; np++) {
                int r = ks * 16 + (lane & 15);
                int c = wn * 64 + np * 16 + ((lane >> 4) << 3);
                uint32_t rh[4];
                ldsm_x4_t(rh, &sBh[slot][r * BSTR + c]);
                bfh[np * 2][0] = rh[0]; bfh[np * 2][1] = rh[1];
                bfh[np * 2 + 1][0] = rh[2]; bfh[np * 2 + 1][1] = rh[3];
                if (NPROD == 3) {
                    uint32_t rl[4];
                    ldsm_x4_t(rl, &sBl[slot][r * BSTR + c]);
                    bfl[np * 2][0] = rl[0]; bfl[np * 2][1] = rl[1];
                    bfl[np * 2 + 1][0] = rl[2]; bfl[np * 2 + 1][1] = rl[3];
                }
            }
#pragma unroll
            for (int mt = 0; mt < 4; mt++)
#pragma unroll
                for (int nt = 0; nt < 8; nt++) {
                    mma16816(acc[mt][nt], afh[mt], bfh[nt]);   // hh
                    mma16816(acc[mt][nt], afl[mt], bfh[nt]);   // lh
                    if (NPROD == 3)
                        mma16816(acc[mt][nt], afh[mt], bfl[nt]);  // hl
                }
        }
        slot++; if (slot >= NSTG) slot -= NSTG;
    }

    float* Cz = C + (size_t)blockIdx.z * ((size_t)BATCH * ldc);
#pragma unroll
    for (int mt = 0; mt < 4; mt++) {
#pragma unroll
        for (int nt = 0; nt < 8; nt++) {
            int col = n0 + wn * 64 + nt * 8 + (lane & 3) * 2;
            if (col >= Nreal) continue;
            float b0 = 0.f, b1 = 0.f;
            if (ACT != ACT_RAW) { b0 = bias[col]; b1 = bias[col + 1]; }
#pragma unroll
            for (int h = 0; h < 2; h++) {
                int row = m0 + wm * 64 + mt * 16 + (lane >> 2) + h * 8;
                float v0 = acc[mt][nt][2 * h + 0] + b0;
                float v1 = acc[mt][nt][2 * h + 1] + b1;
                if (ACT == ACT_TANH) { v0 = tanhf(v0); v1 = tanhf(v1); }
                *(float2*)&Cz[(size_t)row * ldc + col] = make_float2(v0, v1);
            }
        }
    }
}

// ---------------- coalesced split-K combine -> elu -> fp16 hi/lo -----------
// one block per batch row; float4 lanes over the padded width (same
// summation order as before: bias first, slices z=0..NS-1 ascending).
template <int NS>
__global__ void reduce_elu_split2(const float* __restrict__ ws, int ldw,
                                  const float* __restrict__ bias,
                                  __half* __restrict__ hi,
                                  __half* __restrict__ lo,
                                  int Nreal, int Npad)
{
    int m = blockIdx.x;
    int n = threadIdx.x * 4;
    if (n >= Npad) return;
    float v[4] = {0.f, 0.f, 0.f, 0.f};
    if (n < Nreal) {                       // Nreal % 4 == 0 (900, 300)
        float4 b4 = *(const float4*)&bias[n];
        v[0] = b4.x; v[1] = b4.y; v[2] = b4.z; v[3] = b4.w;
        const float* row = ws + (size_t)m * ldw + n;
#pragma unroll
        for (int z = 0; z < NS; z++) {
            float4 w4 = *(const float4*)&row[(size_t)z * BATCH * ldw];
            v[0] += w4.x; v[1] += w4.y; v[2] += w4.z; v[3] += w4.w;
        }
#pragma unroll
        for (int i = 0; i < 4; i++) v[i] = v[i] > 0.f ? v[i] : expm1f(v[i]);
    }
    store_split4(hi, lo, (size_t)m * Npad + n, v);
}

// ---------------- fused latent chain ----------------------------------------
__global__ void __launch_bounds__(256)
latent_chain_kernel(const float* __restrict__ ws2, int ldw,
                    const float* __restrict__ b2,
                    const float* __restrict__ lw, const float* __restrict__ lb,
                    const float* __restrict__ W,
                    const float* __restrict__ noise,
                    const float* __restrict__ dw1, const float* __restrict__ db1,
                    float* __restrict__ lv_o, float* __restrict__ z_o,
                    float* __restrict__ bz_o, float* __restrict__ bm_o,
                    __half* __restrict__ g1h, __half* __restrict__ g1l)
{
    if (blockIdx.x == gridDim.x - 1) {        // Bmat block
        int t = threadIdx.x;
        int i = t >> 4, j = t & 15;
        bm_o[t] = (j > i) ? W[t] * (float)(j - i) : 0.f;
        return;
    }

    const int lane = threadIdx.x & 31;
    const int b = blockIdx.x * 8 + (threadIdx.x >> 5);

    float acc[D];
#pragma unroll
    for (int j = 0; j < D; j++) acc[j] = 0.f;

#pragma unroll
    for (int tt = 0; tt < 10; tt++) {
        int k = lane + tt * 32;
        if (k < H2) {
            size_t o = (size_t)b * ldw + k;
            float hv = b2[k];
#pragma unroll
            for (int z = 0; z < 3; z++)
                hv += ws2[(size_t)z * BATCH * ldw + o];
            hv = hv > 0.f ? hv : expm1f(hv);
#pragma unroll
            for (int j4 = 0; j4 < 4; j4++) {
                float4 w = *(const float4*)&lw[(size_t)k * D + j4 * 4];
                acc[j4 * 4 + 0] = fmaf(hv, w.x, acc[j4 * 4 + 0]);
                acc[j4 * 4 + 1] = fmaf(hv, w.y, acc[j4 * 4 + 1]);
                acc[j4 * 4 + 2] = fmaf(hv, w.z, acc[j4 * 4 + 2]);
                acc[j4 * 4 + 3] = fmaf(hv, w.w, acc[j4 * 4 + 3]);
            }
        }
    }
#pragma unroll
    for (int off = 16; off > 0; off >>= 1)
#pragma unroll
        for (int j = 0; j < D; j++)
            acc[j] += __shfl_xor_sync(0xFFFFFFFF, acc[j], off);

#pragma unroll
    for (int j = 0; j < D; j++) acc[j] += lb[j];

    float eps[D], zz[D], bz[D];
#pragma unroll
    for (int j = 0; j < D; j++)
        eps[j] = expf(0.5f * acc[j]) * noise[(size_t)b * D + j];
#pragma unroll
    for (int j = 0; j < D; j++) {
        float s = 0.f;
#pragma unroll
        for (int i = 0; i < D; i++)
            if (i < j) s = fmaf(zz[i], W[i * D + j] * (float)(j - i), s);
        bz[j] = s;
        zz[j] = eps[j] + s;
    }
    if (lane < D) {
        lv_o[(size_t)b * D + lane] = acc[lane];
        z_o [(size_t)b * D + lane] = zz[lane];
        bz_o[(size_t)b * D + lane] = bz[lane];
    }

    // dec1: g1 = elu(z @ dw1 + db1), padded to H2K, fp16 hi/lo
#pragma unroll
    for (int tt = 0; tt < H2K / 32; tt++) {
        int c = lane + tt * 32;
        float v = 0.f;
        if (c < H2) {
            v = db1[c];
#pragma unroll
            for (int k = 0; k < D; k++)
                v = fmaf(zz[k], dw1[k * H2 + c], v);
            v = v > 0.f ? v : expm1f(v);
        }
        __half h = __float2half_rn(v);
        size_t o = (size_t)b * H2K + c;
        g1h[o] = h;
        g1l[o] = __float2half_rn(v - __half2float(h));
    }
}

// ---------------- launch -----------------------------------------------------
extern "C" void kernel_launch(void* const* d_in, const int* in_sizes, int n_in,
                              void* d_out, int out_size)
{
    (void)in_sizes; (void)n_in; (void)out_size;

    const float* x        = (const float*)d_in[0];
    const float* noise    = (const float*)d_in[1];
    const float* enc_w1   = (const float*)d_in[2];
    const float* enc_b1   = (const float*)d_in[3];
    const float* enc_w2   = (const float*)d_in[4];
    const float* enc_b2   = (const float*)d_in[5];
    const float* logvar_w = (const float*)d_in[6];
    const float* logvar_b = (const float*)d_in[7];
    const float* W        = (const float*)d_in[8];
    const float* dec_w1   = (const float*)d_in[9];
    const float* dec_b1   = (const float*)d_in[10];
    const float* dec_w2   = (const float*)d_in[11];
    const float* dec_b2   = (const float*)d_in[12];
    const float* dec_w3   = (const float*)d_in[13];
    const float* dec_b3   = (const float*)d_in[14];

    float* out  = (float*)d_out;
    float* z_o  = out;
    float* lv_o = out + BATCH * D;
    float* bz_o = out + 2 * BATCH * D;
    float* bm_o = out + 3 * BATCH * D;
    float* xh_o = out + 3 * BATCH * D + D * D;

    float* ws;
    cudaGetSymbolAddress((void**)&ws, g_ws);
    __half *xh, *xl, *w1h, *h1h, *h1l, *w2h, *w2l;
    __half *g1h, *g1l, *dw2h, *dw2l, *g2h, *g2l, *w3h, *w3l;
    cudaGetSymbolAddress((void**)&xh,   g_xh);
    cudaGetSymbolAddress((void**)&xl,   g_xl);
    cudaGetSymbolAddress((void**)&w1h,  g_w1h);
    cudaGetSymbolAddress((void**)&h1h,  g_h1h);
    cudaGetSymbolAddress((void**)&h1l,  g_h1l);
    cudaGetSymbolAddress((void**)&w2h,  g_w2h);
    cudaGetSymbolAddress((void**)&w2l,  g_w2l);
    cudaGetSymbolAddress((void**)&g1h,  g_g1h);
    cudaGetSymbolAddress((void**)&g1l,  g_g1l);
    cudaGetSymbolAddress((void**)&dw2h, g_dw2h);
    cudaGetSymbolAddress((void**)&dw2l, g_dw2l);
    cudaGetSymbolAddress((void**)&g2h,  g_g2h);
    cudaGetSymbolAddress((void**)&g2l,  g_g2l);
    cudaGetSymbolAddress((void**)&w3h,  g_w3h);
    cudaGetSymbolAddress((void**)&w3l,  g_w3l);

    cudaFuncSetAttribute((const void*)mma_gemm_big<ACT_RAW, 2>,
                         cudaFuncAttributeMaxDynamicSharedMemorySize, SMEM_BYTES);
    cudaFuncSetAttribute((const void*)mma_gemm_big<ACT_RAW, 3>,
                         cudaFuncAttributeMaxDynamicSharedMemorySize, SMEM_BYTES);
    cudaFuncSetAttribute((const void*)mma_gemm_big<ACT_TANH, 3>,
                         cudaFuncAttributeMaxDynamicSharedMemorySize, SMEM_BYTES);

    dim3 blk(256);

    // ---- operand prep
    split_half_v4<<<dim3(IMG / 1024, BATCH), blk>>>(x, xh, xl, BATCH, IMG, IMG);
    conv_half_v4<<<dim3(1, IMG), blk>>>(enc_w1, w1h, IMG, H1, W1N);
    split_half_v4<<<dim3(1, H1K), blk>>>(enc_w2, w2h, w2l, H1, H2, H2N);
    split_half_v4<<<dim3(1, H2K), blk>>>(dec_w2, dw2h, dw2l, H2, H2, H2N);
    split_half_v4<<<dim3(IMG / 1024, H2K), blk>>>(dec_w3, w3h, w3l, H2, IMG, IMG);

    // ---- enc1: 2-product, split-K=4
    {
        int kt = IMG / (4 * TBK);                 // 216
        mma_gemm_big<ACT_RAW, 2><<<dim3(W1N / TBN, BATCH / TBM, 4), 128, SMEM_BYTES>>>(
            xh, xl, IMG, w1h, nullptr, W1N, nullptr, ws, W1N, W1N, kt, kt);
    }
    reduce_elu_split2<4><<<BATCH, H1K / 4>>>(ws, W1N, enc_b1, h1h, h1l, H1, H1K);

    // ---- enc2: 3-product, 3 K-slices of 10 kt
    mma_gemm_big<ACT_RAW, 3><<<dim3(H2N / TBN, BATCH / TBM, 3), 128, SMEM_BYTES>>>(
        h1h, h1l, H1K, w2h, w2l, H2N, nullptr, ws, H2N, H2N, 10, 10);

    // ---- fused latent chain (h2 sum + logvar + solve + dec1 + Bmat)
    latent_chain_kernel<<<BATCH / 8 + 1, blk>>>(
        ws, H2N, enc_b2, logvar_w, logvar_b, W, noise, dec_w1, dec_b1,
        lv_o, z_o, bz_o, bm_o, g1h, g1l);

    // ---- dec2: 3-product, 2 K-slices of 5 kt
    mma_gemm_big<ACT_RAW, 3><<<dim3(H2N / TBN, BATCH / TBM, 2), 128, SMEM_BYTES>>>(
        g1h, g1l, H2K, dw2h, dw2l, H2N, nullptr, ws, H2N, H2N, 5, 5);
    reduce_elu_split2<2><<<BATCH, H2K / 4>>>(ws, H2N, dec_b2, g2h, g2l, H2, H2K);

    // ---- dec3: 3-product, tanh
    mma_gemm_big<ACT_TANH, 3><<<dim3(IMG / TBN, BATCH / TBM, 1), 128, SMEM_BYTES>>>(
        g2h, g2l, H2K, w3h, w3l, IMG, dec_b3, xh_o, IMG, IMG, H2K / TBK, H2K / TBK);
}